// round 1
// baseline (speedup 1.0000x reference)
#include <cuda_runtime.h>
#include <cstdint>

// Problem constants (fixed shapes per reference)
#define NN 16
#define LL 512
#define CC 256          // E == F == 256
#define KK 768          // 3 taps * 256 channels
#define MM 4096         // mel_max_length
#define ROWS (NN*LL)    // 8192

// GEMM tiling
#define BM 64
#define BN 64
#define BKC 32
#define XS_STRIDE 260   // 256 + 4 pad to break bank conflicts
#define GEMM_SMEM_FLOATS ((BM+2)*XS_STRIDE + BKC*BN)
#define GEMM_SMEM_BYTES (GEMM_SMEM_FLOATS*4)

// ---------------- device scratch ----------------
__device__ float g_wT1[KK*CC];
__device__ float g_wT2[KK*CC];
__device__ float g_h1[ROWS*CC];
__device__ float g_h2[ROWS*CC];
__device__ int   g_cum[NN*LL];

// ---------------- weight transpose: w[f][e][k] -> wT[k*256+e][f] ----------------
__global__ void transpose_w_kernel(const float* __restrict__ w, float* __restrict__ wT) {
    int idx = blockIdx.x * 256 + threadIdx.x;   // over KK*CC = 196608
    if (idx >= KK*CC) return;
    int f    = idx & 255;
    int kidx = idx >> 8;        // 0..767
    int e    = kidx & 255;
    int ktap = kidx >> 8;       // 0..2
    wT[idx] = w[f*768 + e*3 + ktap];
}

// ---------------- conv-as-GEMM (fp32, smem tiled, 4x4 microtile) ----------------
// out[row, f] = sum_{ktap,e} in[n, l+ktap-1, e] * wT[ktap*256+e, f] + bias[f]
__global__ void __launch_bounds__(256)
conv_gemm_kernel(const float* __restrict__ in, const float* __restrict__ wT,
                 const float* __restrict__ bias, float* __restrict__ out) {
    extern __shared__ float sm[];
    float* xs = sm;                       // (BM+2) x XS_STRIDE
    float* ws = sm + (BM+2)*XS_STRIDE;    // BKC x BN

    const int rowTile = blockIdx.x;             // 0..127
    const int n  = (rowTile * BM) / LL;
    const int l0 = (rowTile * BM) % LL;
    const int f0 = blockIdx.y * BN;
    const int tid = threadIdx.x;
    const int tx = tid & 15, ty = tid >> 4;

    // Load x tile rows l0-1 .. l0+BM (66 rows x 256 cols), zero-padded at seq edges
    for (int idx = tid; idx < (BM+2)*64; idx += 256) {
        int r  = idx >> 6;        // 0..65
        int c4 = idx & 63;        // float4 column
        int l = l0 - 1 + r;
        float4 v = make_float4(0.f, 0.f, 0.f, 0.f);
        if (l >= 0 && l < LL)
            v = reinterpret_cast<const float4*>(in + ((size_t)(n*LL + l))*CC)[c4];
        *reinterpret_cast<float4*>(xs + r*XS_STRIDE + c4*4) = v;
    }

    float acc[4][4];
    #pragma unroll
    for (int i = 0; i < 4; i++)
        #pragma unroll
        for (int j = 0; j < 4; j++) acc[i][j] = 0.f;

    for (int k0 = 0; k0 < KK; k0 += BKC) {
        __syncthreads();   // also covers initial xs stores
        // load weight chunk: rows k0..k0+31, cols f0..f0+63 (512 float4s)
        for (int idx = tid; idx < BKC*16; idx += 256) {
            int kr = idx >> 4, c4 = idx & 15;
            *reinterpret_cast<float4*>(ws + kr*BN + c4*4) =
                reinterpret_cast<const float4*>(wT + (size_t)(k0+kr)*CC + f0)[c4];
        }
        __syncthreads();

        const int ktap = k0 >> 8;       // constant within a 32-chunk (256 % 32 == 0)
        const int e0   = k0 & 255;
        const float* xbase = xs + (ty*4 + ktap)*XS_STRIDE + e0;

        #pragma unroll
        for (int kk = 0; kk < BKC; kk++) {
            float4 wv = *reinterpret_cast<const float4*>(ws + kk*BN + tx*4);
            float xv0 = xbase[0*XS_STRIDE + kk];
            float xv1 = xbase[1*XS_STRIDE + kk];
            float xv2 = xbase[2*XS_STRIDE + kk];
            float xv3 = xbase[3*XS_STRIDE + kk];
            acc[0][0] += xv0*wv.x; acc[0][1] += xv0*wv.y; acc[0][2] += xv0*wv.z; acc[0][3] += xv0*wv.w;
            acc[1][0] += xv1*wv.x; acc[1][1] += xv1*wv.y; acc[1][2] += xv1*wv.z; acc[1][3] += xv1*wv.w;
            acc[2][0] += xv2*wv.x; acc[2][1] += xv2*wv.y; acc[2][2] += xv2*wv.z; acc[2][3] += xv2*wv.w;
            acc[3][0] += xv3*wv.x; acc[3][1] += xv3*wv.y; acc[3][2] += xv3*wv.z; acc[3][3] += xv3*wv.w;
        }
    }

    const int gr0 = n*LL + l0;
    float4 bv = *reinterpret_cast<const float4*>(bias + f0 + tx*4);
    #pragma unroll
    for (int i = 0; i < 4; i++) {
        float4 o;
        o.x = acc[i][0] + bv.x; o.y = acc[i][1] + bv.y;
        o.z = acc[i][2] + bv.z; o.w = acc[i][3] + bv.w;
        reinterpret_cast<float4*>(out + (size_t)(gr0 + ty*4 + i)*CC + f0)[tx] = o;
    }
}

// ---------------- LayerNorm + ReLU (in place), one block per row ----------------
__global__ void __launch_bounds__(256)
ln_relu_kernel(float* __restrict__ h, const float* __restrict__ g, const float* __restrict__ b) {
    __shared__ float sA[8], sB[8];
    __shared__ float s_mu, s_rstd;
    const int row = blockIdx.x, tid = threadIdx.x;
    float v = h[(size_t)row*CC + tid];
    float a = v, q = v*v;
    #pragma unroll
    for (int off = 16; off; off >>= 1) {
        a += __shfl_down_sync(0xffffffffu, a, off);
        q += __shfl_down_sync(0xffffffffu, q, off);
    }
    const int warp = tid >> 5, lane = tid & 31;
    if (lane == 0) { sA[warp] = a; sB[warp] = q; }
    __syncthreads();
    if (tid == 0) {
        float sa = 0.f, sq = 0.f;
        #pragma unroll
        for (int i = 0; i < 8; i++) { sa += sA[i]; sq += sB[i]; }
        float mu  = sa * (1.f/256.f);
        float var = sq * (1.f/256.f) - mu*mu;
        s_mu = mu; s_rstd = rsqrtf(var + 1e-5f);
    }
    __syncthreads();
    float o = (v - s_mu) * s_rstd * g[tid] + b[tid];
    h[(size_t)row*CC + tid] = fmaxf(o, 0.f);
}

// ---------------- LN2 + ReLU + dot(lin_w) + ReLU -> dur_out ----------------
__global__ void __launch_bounds__(256)
ln_relu_dot_kernel(const float* __restrict__ h, const float* __restrict__ g,
                   const float* __restrict__ b, const float* __restrict__ lw,
                   const float* __restrict__ lb, float* __restrict__ dur) {
    __shared__ float sA[8], sB[8];
    __shared__ float s_mu, s_rstd;
    const int row = blockIdx.x, tid = threadIdx.x;
    float v = h[(size_t)row*CC + tid];
    float a = v, q = v*v;
    #pragma unroll
    for (int off = 16; off; off >>= 1) {
        a += __shfl_down_sync(0xffffffffu, a, off);
        q += __shfl_down_sync(0xffffffffu, q, off);
    }
    const int warp = tid >> 5, lane = tid & 31;
    if (lane == 0) { sA[warp] = a; sB[warp] = q; }
    __syncthreads();
    if (tid == 0) {
        float sa = 0.f, sq = 0.f;
        #pragma unroll
        for (int i = 0; i < 8; i++) { sa += sA[i]; sq += sB[i]; }
        float mu  = sa * (1.f/256.f);
        float var = sq * (1.f/256.f) - mu*mu;
        s_mu = mu; s_rstd = rsqrtf(var + 1e-5f);
    }
    __syncthreads();
    float o = fmaxf((v - s_mu) * s_rstd * g[tid] + b[tid], 0.f);
    float p = o * lw[tid];
    #pragma unroll
    for (int off = 16; off; off >>= 1)
        p += __shfl_down_sync(0xffffffffu, p, off);
    __syncthreads();                 // before reusing sA
    if (lane == 0) sA[warp] = p;
    __syncthreads();
    if (tid == 0) {
        float s = 0.f;
        #pragma unroll
        for (int i = 0; i < 8; i++) s += sA[i];
        dur[row] = fmaxf(s + lb[0], 0.f);
    }
}

// ---------------- inclusive cumsum of target per batch ----------------
__global__ void __launch_bounds__(512)
scan_kernel(const int* __restrict__ target, int* __restrict__ cum) {
    __shared__ int s[LL];
    const int n = blockIdx.x, t = threadIdx.x;
    s[t] = target[n*LL + t];
    __syncthreads();
    for (int off = 1; off < LL; off <<= 1) {
        int add = (t >= off) ? s[t - off] : 0;
        __syncthreads();
        s[t] += add;
        __syncthreads();
    }
    cum[n*LL + t] = s[t];
}

// ---------------- length regulation: out[n,t,:] = x[n,j(t),:] or 0 ----------------
__global__ void __launch_bounds__(256)
regulate_kernel(const float* __restrict__ x, const int* __restrict__ cum,
                float* __restrict__ out) {
    __shared__ int sc[LL];
    const int n  = blockIdx.y;
    const int t0 = blockIdx.x * 32;
    for (int i = threadIdx.x; i < LL; i += 256) sc[i] = cum[n*LL + i];
    __syncthreads();
    const int warp = threadIdx.x >> 5, lane = threadIdx.x & 31;
    const int total = sc[LL - 1];
    #pragma unroll
    for (int it = 0; it < 4; it++) {
        int t = t0 + warp*4 + it;
        int j = -1;
        if (t < total) {   // first j with cum[j] > t
            int lo = 0, hi = LL - 1;
            while (lo < hi) { int mid = (lo + hi) >> 1; if (sc[mid] > t) hi = mid; else lo = mid + 1; }
            j = lo;
        }
        const float4* src = (j >= 0)
            ? reinterpret_cast<const float4*>(x + (size_t)(n*LL + j)*CC) : nullptr;
        float4* dst = reinterpret_cast<float4*>(out + ((size_t)n*MM + t)*CC);
        #pragma unroll
        for (int c = 0; c < 2; c++) {
            float4 v = (j >= 0) ? src[lane + c*32] : make_float4(0.f, 0.f, 0.f, 0.f);
            dst[lane + c*32] = v;
        }
    }
}

// ---------------- launch ----------------
extern "C" void kernel_launch(void* const* d_in, const int* in_sizes, int n_in,
                              void* d_out, int out_size) {
    const float* x       = (const float*)d_in[0];
    const float* conv1_w = (const float*)d_in[1];
    const float* conv1_b = (const float*)d_in[2];
    const float* ln1_g   = (const float*)d_in[3];
    const float* ln1_b   = (const float*)d_in[4];
    const float* conv2_w = (const float*)d_in[5];
    const float* conv2_b = (const float*)d_in[6];
    const float* ln2_g   = (const float*)d_in[7];
    const float* ln2_b   = (const float*)d_in[8];
    const float* lin_w   = (const float*)d_in[9];
    const float* lin_b   = (const float*)d_in[10];
    const int*   target  = (const int*)d_in[11];
    (void)n_in; (void)in_sizes;

    float* out_mel = (float*)d_out;                                   // [N, M, E]
    float* dur_out = (float*)d_out + ((size_t)out_size - NN*LL);      // [N, L]

    float *wT1, *wT2, *h1, *h2; int* cum;
    cudaGetSymbolAddress((void**)&wT1, g_wT1);
    cudaGetSymbolAddress((void**)&wT2, g_wT2);
    cudaGetSymbolAddress((void**)&h1,  g_h1);
    cudaGetSymbolAddress((void**)&h2,  g_h2);
    cudaGetSymbolAddress((void**)&cum, g_cum);

    cudaFuncSetAttribute(conv_gemm_kernel,
                         cudaFuncAttributeMaxDynamicSharedMemorySize, GEMM_SMEM_BYTES);

    // Weight transposes (reads tiny, every call for determinism)
    transpose_w_kernel<<<KK*CC/256, 256>>>(conv1_w, wT1);
    transpose_w_kernel<<<KK*CC/256, 256>>>(conv2_w, wT2);

    // Duration predictor
    dim3 ggrid(ROWS/BM, CC/BN);
    conv_gemm_kernel<<<ggrid, 256, GEMM_SMEM_BYTES>>>(x,  wT1, conv1_b, h1);
    ln_relu_kernel<<<ROWS, 256>>>(h1, ln1_g, ln1_b);
    conv_gemm_kernel<<<ggrid, 256, GEMM_SMEM_BYTES>>>(h1, wT2, conv2_b, h2);
    ln_relu_dot_kernel<<<ROWS, 256>>>(h2, ln2_g, ln2_b, lin_w, lin_b, dur_out);

    // Length regulation
    scan_kernel<<<NN, LL>>>(target, cum);
    dim3 rgrid(MM/32, NN);
    regulate_kernel<<<rgrid, 256>>>(x, cum, out_mel);
}

// round 4
// speedup vs baseline: 1.9812x; 1.9812x over previous
#include <cuda_runtime.h>
#include <cuda_bf16.h>
#include <mma.h>
#include <cstdint>

using namespace nvcuda;

// Problem constants
#define NN 16
#define LL 512
#define CC 256          // E == F == 256
#define MM 4096         // mel_max_length
#define ROWS (NN*LL)    // 8192
#define KTOT 768        // 3 taps * 256
#define EPS 1e-5f

// GEMM tiling: CTA = 64(M) x 256(N), K-chunk 32, 8 warps (2Mx4N), warp tile 32x64
#define BM 64
#define KC 32
#define A_STRIDE 40      // bf16 elems (80B)
#define B_STRIDE 264     // bf16 elems (528B)
#define C_STRIDE 260     // f32 elems (1040B)

#define A_BYTES (BM*A_STRIDE*2)      // 5120
#define B_BYTES (KC*B_STRIDE*2)      // 16896

// dynamic smem layout (bytes): params | A hi/lo x2 | B hi/lo x2 | C
#define SM_PAR 0
#define SM_AH0 4096
#define SM_AL0 (SM_AH0 + A_BYTES)
#define SM_AH1 (SM_AL0 + A_BYTES)
#define SM_AL1 (SM_AH1 + A_BYTES)
#define SM_BH0 (SM_AL1 + A_BYTES)
#define SM_BL0 (SM_BH0 + B_BYTES)
#define SM_BH1 (SM_BL0 + B_BYTES)
#define SM_BL1 (SM_BH1 + B_BYTES)
#define SM_C   (SM_BL1 + B_BYTES)
#define SM_TOTAL (SM_C + BM*C_STRIDE*4)   // 158720

__device__ __forceinline__ uint32_t smem_to_u32(const void* p) {
    uint32_t a;
    asm("{ .reg .u64 t; cvta.to.shared.u64 t, %1; cvt.u32.u64 %0, t; }" : "=r"(a) : "l"(p));
    return a;
}

// ---------------- device scratch ----------------
__device__ __nv_bfloat16 g_xh [ROWS*CC], g_xl [ROWS*CC];   // x hi/lo
__device__ __nv_bfloat16 g_h1h[ROWS*CC], g_h1l[ROWS*CC];   // h1 hi/lo
__device__ __nv_bfloat16 g_w1h[KTOT*CC], g_w1l[KTOT*CC];   // B[k][f]
__device__ __nv_bfloat16 g_w2h[KTOT*CC], g_w2l[KTOT*CC];
__device__ int g_cum[NN*LL];

// ---------------- prep: x fp32 -> bf16 hi/lo ----------------
__global__ void __launch_bounds__(256)
prep_x_kernel(const float* __restrict__ in,
              __nv_bfloat16* __restrict__ oh, __nv_bfloat16* __restrict__ ol) {
    int idx = blockIdx.x * 256 + threadIdx.x;          // over (ROWS*CC)/4
    float4 v = reinterpret_cast<const float4*>(in)[idx];
    float f[4] = {v.x, v.y, v.z, v.w};
    __nv_bfloat16 h[4], l[4];
    #pragma unroll
    for (int k = 0; k < 4; k++) {
        h[k] = __float2bfloat16(f[k]);
        l[k] = __float2bfloat16(f[k] - __bfloat162float(h[k]));
    }
    uint2 uh, ul;
    __nv_bfloat162 t;
    t = __nv_bfloat162(h[0], h[1]); uh.x = *reinterpret_cast<uint32_t*>(&t);
    t = __nv_bfloat162(h[2], h[3]); uh.y = *reinterpret_cast<uint32_t*>(&t);
    t = __nv_bfloat162(l[0], l[1]); ul.x = *reinterpret_cast<uint32_t*>(&t);
    t = __nv_bfloat162(l[2], l[3]); ul.y = *reinterpret_cast<uint32_t*>(&t);
    reinterpret_cast<uint2*>(oh)[idx] = uh;
    reinterpret_cast<uint2*>(ol)[idx] = ul;
}

// ---------------- prep: w[f][e][3] -> B[ktap*256+e][f] bf16 hi/lo ----------------
__global__ void __launch_bounds__(256)
prep_w_kernel(const float* __restrict__ w,
              __nv_bfloat16* __restrict__ Bh, __nv_bfloat16* __restrict__ Bl) {
    int idx = blockIdx.x * 256 + threadIdx.x;          // over KTOT*CC
    int f = idx & 255;
    int k = idx >> 8;            // 0..767
    int e = k & 255;
    int ktap = k >> 8;
    float v = w[f * KTOT + e * 3 + ktap];
    __nv_bfloat16 h = __float2bfloat16(v);
    Bh[idx] = h;
    Bl[idx] = __float2bfloat16(v - __bfloat162float(h));
}

// ---------------- tile loader (cp.async, 16B) ----------------
__device__ __forceinline__ void load_tile(
    uint32_t Ah, uint32_t Al, uint32_t Bh, uint32_t Bl,
    const __nv_bfloat16* __restrict__ xh, const __nv_bfloat16* __restrict__ xl,
    const __nv_bfloat16* __restrict__ wh, const __nv_bfloat16* __restrict__ wl,
    int n, int l0, int chunk, int tid)
{
    const int k0 = chunk * KC;
    const int ktap = k0 >> 8;        // KC=32 divides 256: no tap crossing
    const int e0 = k0 & 255;
    // A: 64 rows x 32 bf16; one 16B chunk per thread, hi + lo
    {
        int r = tid >> 2, c4 = tid & 3;
        int l = l0 + r + ktap - 1;
        int ok = (l >= 0 && l < LL);
        size_t off = (size_t)(n * LL + (ok ? l : 0)) * CC + e0 + c4 * 8;
        uint32_t doff = (uint32_t)(r * (A_STRIDE * 2) + c4 * 16);
        int sz = ok ? 16 : 0;
        asm volatile("cp.async.cg.shared.global [%0], [%1], 16, %2;"
                     :: "r"(Ah + doff), "l"(xh + off), "r"(sz));
        asm volatile("cp.async.cg.shared.global [%0], [%1], 16, %2;"
                     :: "r"(Al + doff), "l"(xl + off), "r"(sz));
    }
    // B: 32 rows(k) x 256 cols(f); 4 x 16B per thread, hi + lo
    #pragma unroll
    for (int i = 0; i < 4; i++) {
        int idx = tid + i * 256;
        int kr = idx >> 5, c4 = idx & 31;
        size_t off = (size_t)(k0 + kr) * CC + c4 * 8;
        uint32_t doff = (uint32_t)(kr * (B_STRIDE * 2) + c4 * 16);
        asm volatile("cp.async.cg.shared.global [%0], [%1], 16, %2;"
                     :: "r"(Bh + doff), "l"(wh + off), "r"(16));
        asm volatile("cp.async.cg.shared.global [%0], [%1], 16, %2;"
                     :: "r"(Bl + doff), "l"(wl + off), "r"(16));
    }
}

// ---------------- fused conv3 GEMM (bf16x3) + bias + LN + ReLU (+dot) ----------------
template <int MODE>  // 0: write bf16 hi/lo hout; 1: LN+relu+dot(lw)+relu -> dur
__global__ void __launch_bounds__(256)
conv_wmma_kernel(const __nv_bfloat16* __restrict__ xh, const __nv_bfloat16* __restrict__ xl,
                 const __nv_bfloat16* __restrict__ wh, const __nv_bfloat16* __restrict__ wl,
                 const float* __restrict__ bias,
                 const float* __restrict__ lng, const float* __restrict__ lnb,
                 const float* __restrict__ lw, const float* __restrict__ lb,
                 __nv_bfloat16* __restrict__ houth, __nv_bfloat16* __restrict__ houtl,
                 float* __restrict__ dur)
{
    extern __shared__ char smem[];
    const int tid = threadIdx.x;
    const int wid = tid >> 5;
    const int lane = tid & 31;

    const int rows0 = blockIdx.x * BM;
    const int n  = rows0 >> 9;
    const int l0 = rows0 & 511;

    float* sBias = (float*)(smem + SM_PAR);
    float* sG    = sBias + 256;
    float* sB    = sG + 256;
    float* sLw   = sB + 256;
    sBias[tid] = bias[tid];
    sG[tid] = lng[tid];
    sB[tid] = lnb[tid];
    if (MODE == 1) sLw[tid] = lw[tid];

    const uint32_t sbase = smem_to_u32(smem);
    const uint32_t AhB[2] = { sbase + SM_AH0, sbase + SM_AH1 };
    const uint32_t AlB[2] = { sbase + SM_AL0, sbase + SM_AL1 };
    const uint32_t BhB[2] = { sbase + SM_BH0, sbase + SM_BH1 };
    const uint32_t BlB[2] = { sbase + SM_BL0, sbase + SM_BL1 };
    const __nv_bfloat16* AhP[2] = { (const __nv_bfloat16*)(smem + SM_AH0),
                                    (const __nv_bfloat16*)(smem + SM_AH1) };
    const __nv_bfloat16* AlP[2] = { (const __nv_bfloat16*)(smem + SM_AL0),
                                    (const __nv_bfloat16*)(smem + SM_AL1) };
    const __nv_bfloat16* BhP[2] = { (const __nv_bfloat16*)(smem + SM_BH0),
                                    (const __nv_bfloat16*)(smem + SM_BH1) };
    const __nv_bfloat16* BlP[2] = { (const __nv_bfloat16*)(smem + SM_BL0),
                                    (const __nv_bfloat16*)(smem + SM_BL1) };
    float* Cs = (float*)(smem + SM_C);

    const int warpM = wid & 1;        // rows warpM*32
    const int warpN = wid >> 1;       // cols warpN*64

    wmma::fragment<wmma::accumulator, 16, 16, 16, float> acc[2][4];
    #pragma unroll
    for (int mi = 0; mi < 2; mi++)
        #pragma unroll
        for (int ni = 0; ni < 4; ni++)
            wmma::fill_fragment(acc[mi][ni], 0.f);

    // prologue
    load_tile(AhB[0], AlB[0], BhB[0], BlB[0], xh, xl, wh, wl, n, l0, 0, tid);
    asm volatile("cp.async.commit_group;" ::: "memory");

    for (int c = 0; c < 24; c++) {
        asm volatile("cp.async.wait_group 0;" ::: "memory");
        __syncthreads();
        if (c < 23) {
            int nb = (c + 1) & 1;
            load_tile(AhB[nb], AlB[nb], BhB[nb], BlB[nb], xh, xl, wh, wl, n, l0, c + 1, tid);
            asm volatile("cp.async.commit_group;" ::: "memory");
        }
        const __nv_bfloat16* Ahs = AhP[c & 1];
        const __nv_bfloat16* Als = AlP[c & 1];
        const __nv_bfloat16* Bhs = BhP[c & 1];
        const __nv_bfloat16* Bls = BlP[c & 1];
        #pragma unroll
        for (int kk = 0; kk < 2; kk++) {          // two k16 steps
            wmma::fragment<wmma::matrix_a, 16, 16, 16, __nv_bfloat16, wmma::row_major> ah[2], al[2];
            wmma::fragment<wmma::matrix_b, 16, 16, 16, __nv_bfloat16, wmma::row_major> bh[4], bl[4];
            #pragma unroll
            for (int mi = 0; mi < 2; mi++) {
                int ro = (warpM * 32 + mi * 16) * A_STRIDE + kk * 16;
                wmma::load_matrix_sync(ah[mi], Ahs + ro, A_STRIDE);
                wmma::load_matrix_sync(al[mi], Als + ro, A_STRIDE);
            }
            #pragma unroll
            for (int ni = 0; ni < 4; ni++) {
                int co = (kk * 16) * B_STRIDE + warpN * 64 + ni * 16;
                wmma::load_matrix_sync(bh[ni], Bhs + co, B_STRIDE);
                wmma::load_matrix_sync(bl[ni], Bls + co, B_STRIDE);
            }
            #pragma unroll
            for (int mi = 0; mi < 2; mi++)
                #pragma unroll
                for (int ni = 0; ni < 4; ni++) {
                    wmma::mma_sync(acc[mi][ni], ah[mi], bh[ni], acc[mi][ni]);
                    wmma::mma_sync(acc[mi][ni], ah[mi], bl[ni], acc[mi][ni]);
                    wmma::mma_sync(acc[mi][ni], al[mi], bh[ni], acc[mi][ni]);
                }
        }
    }

    // store accums to smem C
    #pragma unroll
    for (int mi = 0; mi < 2; mi++)
        #pragma unroll
        for (int ni = 0; ni < 4; ni++)
            wmma::store_matrix_sync(
                Cs + (warpM * 32 + mi * 16) * C_STRIDE + warpN * 64 + ni * 16,
                acc[mi][ni], C_STRIDE, wmma::mem_row_major);
    __syncthreads();

    // LN + relu epilogue: warp w handles rows w*8..w*8+7; lane owns cols lane*8..+8
    #pragma unroll
    for (int rr = 0; rr < 8; rr++) {
        const int row = wid * 8 + rr;
        const int grow = rows0 + row;
        const float* crow = Cs + row * C_STRIDE;
        float v[8];
        float4 v0 = *reinterpret_cast<const float4*>(crow + lane * 8);
        float4 v1 = *reinterpret_cast<const float4*>(crow + lane * 8 + 4);
        v[0]=v0.x; v[1]=v0.y; v[2]=v0.z; v[3]=v0.w;
        v[4]=v1.x; v[5]=v1.y; v[6]=v1.z; v[7]=v1.w;
        float sum = 0.f, sq = 0.f;
        #pragma unroll
        for (int k = 0; k < 8; k++) {
            v[k] += sBias[lane * 8 + k];
            sum += v[k]; sq += v[k] * v[k];
        }
        #pragma unroll
        for (int off = 16; off; off >>= 1) {
            sum += __shfl_xor_sync(0xffffffffu, sum, off);
            sq  += __shfl_xor_sync(0xffffffffu, sq,  off);
        }
        float mu = sum * (1.f / 256.f);
        float var = sq * (1.f / 256.f) - mu * mu;
        float rstd = rsqrtf(var + EPS);

        if (MODE == 0) {
            uint32_t uh[4], ul[4];
            #pragma unroll
            for (int k = 0; k < 4; k++) {
                float o0 = fmaxf((v[2*k]   - mu) * rstd * sG[lane*8 + 2*k]   + sB[lane*8 + 2*k],   0.f);
                float o1 = fmaxf((v[2*k+1] - mu) * rstd * sG[lane*8 + 2*k+1] + sB[lane*8 + 2*k+1], 0.f);
                __nv_bfloat16 h0 = __float2bfloat16(o0);
                __nv_bfloat16 h1 = __float2bfloat16(o1);
                __nv_bfloat16 s0 = __float2bfloat16(o0 - __bfloat162float(h0));
                __nv_bfloat16 s1 = __float2bfloat16(o1 - __bfloat162float(h1));
                __nv_bfloat162 th(h0, h1), tl(s0, s1);
                uh[k] = *reinterpret_cast<uint32_t*>(&th);
                ul[k] = *reinterpret_cast<uint32_t*>(&tl);
            }
            reinterpret_cast<uint4*>(houth + (size_t)grow * CC)[lane] =
                make_uint4(uh[0], uh[1], uh[2], uh[3]);
            reinterpret_cast<uint4*>(houtl + (size_t)grow * CC)[lane] =
                make_uint4(ul[0], ul[1], ul[2], ul[3]);
        } else {
            float p = 0.f;
            #pragma unroll
            for (int k = 0; k < 8; k++) {
                float o = fmaxf((v[k] - mu) * rstd * sG[lane*8 + k] + sB[lane*8 + k], 0.f);
                p += o * sLw[lane * 8 + k];
            }
            #pragma unroll
            for (int off = 16; off; off >>= 1)
                p += __shfl_xor_sync(0xffffffffu, p, off);
            if (lane == 0) dur[grow] = fmaxf(p + lb[0], 0.f);
        }
    }
}

// ---------------- inclusive cumsum of target per batch ----------------
__global__ void __launch_bounds__(512)
scan_kernel(const int* __restrict__ target, int* __restrict__ cum) {
    __shared__ int s[LL];
    const int n = blockIdx.x, t = threadIdx.x;
    s[t] = target[n * LL + t];
    __syncthreads();
    for (int off = 1; off < LL; off <<= 1) {
        int add = (t >= off) ? s[t - off] : 0;
        __syncthreads();
        s[t] += add;
        __syncthreads();
    }
    cum[n * LL + t] = s[t];
}

// ---------------- length regulation ----------------
__global__ void __launch_bounds__(256)
regulate_kernel(const float* __restrict__ x, const int* __restrict__ cum,
                float* __restrict__ out) {
    __shared__ int sc[LL];
    const int n  = blockIdx.y;
    const int t0 = blockIdx.x * 32;
    for (int i = threadIdx.x; i < LL; i += 256) sc[i] = cum[n * LL + i];
    __syncthreads();
    const int warp = threadIdx.x >> 5, lane = threadIdx.x & 31;
    const int total = sc[LL - 1];
    #pragma unroll
    for (int it = 0; it < 4; it++) {
        int t = t0 + warp * 4 + it;
        int j = -1;
        if (t < total) {
            int lo = 0, hi = LL - 1;
            while (lo < hi) { int mid = (lo + hi) >> 1; if (sc[mid] > t) hi = mid; else lo = mid + 1; }
            j = lo;
        }
        const float4* src = (j >= 0)
            ? reinterpret_cast<const float4*>(x + (size_t)(n * LL + j) * CC) : nullptr;
        float4* dst = reinterpret_cast<float4*>(out + ((size_t)n * MM + t) * CC);
        #pragma unroll
        for (int c = 0; c < 2; c++) {
            float4 v = (j >= 0) ? src[lane + c * 32] : make_float4(0.f, 0.f, 0.f, 0.f);
            dst[lane + c * 32] = v;
        }
    }
}

// ---------------- launch ----------------
extern "C" void kernel_launch(void* const* d_in, const int* in_sizes, int n_in,
                              void* d_out, int out_size) {
    const float* x       = (const float*)d_in[0];
    const float* conv1_w = (const float*)d_in[1];
    const float* conv1_b = (const float*)d_in[2];
    const float* ln1_g   = (const float*)d_in[3];
    const float* ln1_b   = (const float*)d_in[4];
    const float* conv2_w = (const float*)d_in[5];
    const float* conv2_b = (const float*)d_in[6];
    const float* ln2_g   = (const float*)d_in[7];
    const float* ln2_b   = (const float*)d_in[8];
    const float* lin_w   = (const float*)d_in[9];
    const float* lin_b   = (const float*)d_in[10];
    const int*   target  = (const int*)d_in[11];
    (void)n_in; (void)in_sizes;

    float* out_mel = (float*)d_out;                                  // [N, M, E]
    float* dur_out = (float*)d_out + ((size_t)out_size - NN * LL);   // [N, L]

    __nv_bfloat16 *xh, *xl, *h1h, *h1l, *w1h, *w1l, *w2h, *w2l; int* cum;
    cudaGetSymbolAddress((void**)&xh,  g_xh);
    cudaGetSymbolAddress((void**)&xl,  g_xl);
    cudaGetSymbolAddress((void**)&h1h, g_h1h);
    cudaGetSymbolAddress((void**)&h1l, g_h1l);
    cudaGetSymbolAddress((void**)&w1h, g_w1h);
    cudaGetSymbolAddress((void**)&w1l, g_w1l);
    cudaGetSymbolAddress((void**)&w2h, g_w2h);
    cudaGetSymbolAddress((void**)&w2l, g_w2l);
    cudaGetSymbolAddress((void**)&cum, g_cum);

    cudaFuncSetAttribute(conv_wmma_kernel<0>,
                         cudaFuncAttributeMaxDynamicSharedMemorySize, SM_TOTAL);
    cudaFuncSetAttribute(conv_wmma_kernel<1>,
                         cudaFuncAttributeMaxDynamicSharedMemorySize, SM_TOTAL);

    // prep
    prep_x_kernel<<<(ROWS * CC / 4) / 256, 256>>>(x, xh, xl);
    prep_w_kernel<<<(KTOT * CC) / 256, 256>>>(conv1_w, w1h, w1l);
    prep_w_kernel<<<(KTOT * CC) / 256, 256>>>(conv2_w, w2h, w2l);

    // duration predictor (conv+LN+relu fused, WMMA bf16x3)
    conv_wmma_kernel<0><<<ROWS / BM, 256, SM_TOTAL>>>(
        xh, xl, w1h, w1l, conv1_b, ln1_g, ln1_b, nullptr, nullptr, h1h, h1l, nullptr);
    conv_wmma_kernel<1><<<ROWS / BM, 256, SM_TOTAL>>>(
        h1h, h1l, w2h, w2l, conv2_b, ln2_g, ln2_b, lin_w, lin_b, nullptr, nullptr, dur_out);

    // length regulation
    scan_kernel<<<NN, LL>>>(target, cum);
    dim3 rgrid(MM / 32, NN);
    regulate_kernel<<<rgrid, 256>>>(x, cum, out_mel);
}

// round 5
// speedup vs baseline: 1.9837x; 1.0012x over previous
#include <cuda_runtime.h>
#include <cuda_bf16.h>
#include <mma.h>
#include <cstdint>

using namespace nvcuda;

// Problem constants
#define NN 16
#define LL 512
#define CC 256          // E == F == 256
#define MM 4096         // mel_max_length
#define ROWS (NN*LL)    // 8192
#define KTOT 768        // 3 taps * 256
#define EPS 1e-5f

// GEMM tiling: CTA = 64(M) x 256(N), K-chunk 32, 8 warps (2Mx4N), warp tile 32x64
#define BM 64
#define KC 32
#define A_STRIDE 40      // bf16 elems (80B)
#define B_STRIDE 264     // bf16 elems (528B)
#define C_STRIDE 260     // f32 elems (1040B)

#define A_BYTES (BM*A_STRIDE*2)      // 5120
#define B_BYTES (KC*B_STRIDE*2)      // 16896

// dynamic smem layout (bytes): params | A hi/lo x2 | B hi/lo x2 | C
#define SM_PAR 0
#define SM_AH0 4096
#define SM_AL0 (SM_AH0 + A_BYTES)
#define SM_AH1 (SM_AL0 + A_BYTES)
#define SM_AL1 (SM_AH1 + A_BYTES)
#define SM_BH0 (SM_AL1 + A_BYTES)
#define SM_BL0 (SM_BH0 + B_BYTES)
#define SM_BH1 (SM_BL0 + B_BYTES)
#define SM_BL1 (SM_BH1 + B_BYTES)
#define SM_C   (SM_BL1 + B_BYTES)
#define SM_TOTAL (SM_C + BM*C_STRIDE*4)   // 158720

__device__ __forceinline__ uint32_t smem_to_u32(const void* p) {
    uint32_t a;
    asm("{ .reg .u64 t; cvta.to.shared.u64 t, %1; cvt.u32.u64 %0, t; }" : "=r"(a) : "l"(p));
    return a;
}

// ---------------- device scratch ----------------
__device__ __nv_bfloat16 g_xh [ROWS*CC], g_xl [ROWS*CC];   // x hi/lo
__device__ __nv_bfloat16 g_h1h[ROWS*CC], g_h1l[ROWS*CC];   // h1 hi/lo
__device__ __nv_bfloat16 g_w1h[KTOT*CC], g_w1l[KTOT*CC];   // B[k][f]
__device__ __nv_bfloat16 g_w2h[KTOT*CC], g_w2l[KTOT*CC];
__device__ int g_cum[NN*LL];

// ---------------- prep: x fp32 -> bf16 hi/lo ----------------
__global__ void __launch_bounds__(256)
prep_x_kernel(const float* __restrict__ in,
              __nv_bfloat16* __restrict__ oh, __nv_bfloat16* __restrict__ ol) {
    int idx = blockIdx.x * 256 + threadIdx.x;          // over (ROWS*CC)/4
    float4 v = reinterpret_cast<const float4*>(in)[idx];
    float f[4] = {v.x, v.y, v.z, v.w};
    __nv_bfloat16 h[4], l[4];
    #pragma unroll
    for (int k = 0; k < 4; k++) {
        h[k] = __float2bfloat16(f[k]);
        l[k] = __float2bfloat16(f[k] - __bfloat162float(h[k]));
    }
    uint2 uh, ul;
    __nv_bfloat162 t;
    t = __nv_bfloat162(h[0], h[1]); uh.x = *reinterpret_cast<uint32_t*>(&t);
    t = __nv_bfloat162(h[2], h[3]); uh.y = *reinterpret_cast<uint32_t*>(&t);
    t = __nv_bfloat162(l[0], l[1]); ul.x = *reinterpret_cast<uint32_t*>(&t);
    t = __nv_bfloat162(l[2], l[3]); ul.y = *reinterpret_cast<uint32_t*>(&t);
    reinterpret_cast<uint2*>(oh)[idx] = uh;
    reinterpret_cast<uint2*>(ol)[idx] = ul;
}

// ---------------- prep: w[f][e][3] -> B[ktap*256+e][f] bf16 hi/lo ----------------
__global__ void __launch_bounds__(256)
prep_w_kernel(const float* __restrict__ w,
              __nv_bfloat16* __restrict__ Bh, __nv_bfloat16* __restrict__ Bl) {
    int idx = blockIdx.x * 256 + threadIdx.x;          // over KTOT*CC
    int f = idx & 255;
    int k = idx >> 8;            // 0..767
    int e = k & 255;
    int ktap = k >> 8;
    float v = w[f * KTOT + e * 3 + ktap];
    __nv_bfloat16 h = __float2bfloat16(v);
    Bh[idx] = h;
    Bl[idx] = __float2bfloat16(v - __bfloat162float(h));
}

// ---------------- tile loader (cp.async, 16B) ----------------
__device__ __forceinline__ void load_tile(
    uint32_t Ah, uint32_t Al, uint32_t Bh, uint32_t Bl,
    const __nv_bfloat16* __restrict__ xh, const __nv_bfloat16* __restrict__ xl,
    const __nv_bfloat16* __restrict__ wh, const __nv_bfloat16* __restrict__ wl,
    int n, int l0, int chunk, int tid)
{
    const int k0 = chunk * KC;
    const int ktap = k0 >> 8;        // KC=32 divides 256: no tap crossing
    const int e0 = k0 & 255;
    // A: 64 rows x 32 bf16; one 16B chunk per thread, hi + lo
    {
        int r = tid >> 2, c4 = tid & 3;
        int l = l0 + r + ktap - 1;
        int ok = (l >= 0 && l < LL);
        size_t off = (size_t)(n * LL + (ok ? l : 0)) * CC + e0 + c4 * 8;
        uint32_t doff = (uint32_t)(r * (A_STRIDE * 2) + c4 * 16);
        int sz = ok ? 16 : 0;
        asm volatile("cp.async.cg.shared.global [%0], [%1], 16, %2;"
                     :: "r"(Ah + doff), "l"(xh + off), "r"(sz));
        asm volatile("cp.async.cg.shared.global [%0], [%1], 16, %2;"
                     :: "r"(Al + doff), "l"(xl + off), "r"(sz));
    }
    // B: 32 rows(k) x 256 cols(f); 4 x 16B per thread, hi + lo
    #pragma unroll
    for (int i = 0; i < 4; i++) {
        int idx = tid + i * 256;
        int kr = idx >> 5, c4 = idx & 31;
        size_t off = (size_t)(k0 + kr) * CC + c4 * 8;
        uint32_t doff = (uint32_t)(kr * (B_STRIDE * 2) + c4 * 16);
        asm volatile("cp.async.cg.shared.global [%0], [%1], 16, %2;"
                     :: "r"(Bh + doff), "l"(wh + off), "r"(16));
        asm volatile("cp.async.cg.shared.global [%0], [%1], 16, %2;"
                     :: "r"(Bl + doff), "l"(wl + off), "r"(16));
    }
}

// ---------------- fused conv3 GEMM (bf16x3) + bias + LN + ReLU (+dot) ----------------
template <int MODE>  // 0: write bf16 hi/lo hout; 1: LN+relu+dot(lw)+relu -> dur
__global__ void __launch_bounds__(256)
conv_wmma_kernel(const __nv_bfloat16* __restrict__ xh, const __nv_bfloat16* __restrict__ xl,
                 const __nv_bfloat16* __restrict__ wh, const __nv_bfloat16* __restrict__ wl,
                 const float* __restrict__ bias,
                 const float* __restrict__ lng, const float* __restrict__ lnb,
                 const float* __restrict__ lw, const float* __restrict__ lb,
                 __nv_bfloat16* __restrict__ houth, __nv_bfloat16* __restrict__ houtl,
                 float* __restrict__ dur)
{
    extern __shared__ char smem[];
    const int tid = threadIdx.x;
    const int wid = tid >> 5;
    const int lane = tid & 31;

    const int rows0 = blockIdx.x * BM;
    const int n  = rows0 >> 9;
    const int l0 = rows0 & 511;

    float* sBias = (float*)(smem + SM_PAR);
    float* sG    = sBias + 256;
    float* sB    = sG + 256;
    float* sLw   = sB + 256;
    sBias[tid] = bias[tid];
    sG[tid] = lng[tid];
    sB[tid] = lnb[tid];
    if (MODE == 1) sLw[tid] = lw[tid];

    const uint32_t sbase = smem_to_u32(smem);
    const uint32_t AhB[2] = { sbase + SM_AH0, sbase + SM_AH1 };
    const uint32_t AlB[2] = { sbase + SM_AL0, sbase + SM_AL1 };
    const uint32_t BhB[2] = { sbase + SM_BH0, sbase + SM_BH1 };
    const uint32_t BlB[2] = { sbase + SM_BL0, sbase + SM_BL1 };
    const __nv_bfloat16* AhP[2] = { (const __nv_bfloat16*)(smem + SM_AH0),
                                    (const __nv_bfloat16*)(smem + SM_AH1) };
    const __nv_bfloat16* AlP[2] = { (const __nv_bfloat16*)(smem + SM_AL0),
                                    (const __nv_bfloat16*)(smem + SM_AL1) };
    const __nv_bfloat16* BhP[2] = { (const __nv_bfloat16*)(smem + SM_BH0),
                                    (const __nv_bfloat16*)(smem + SM_BH1) };
    const __nv_bfloat16* BlP[2] = { (const __nv_bfloat16*)(smem + SM_BL0),
                                    (const __nv_bfloat16*)(smem + SM_BL1) };
    float* Cs = (float*)(smem + SM_C);

    const int warpM = wid & 1;        // rows warpM*32
    const int warpN = wid >> 1;       // cols warpN*64

    wmma::fragment<wmma::accumulator, 16, 16, 16, float> acc[2][4];
    #pragma unroll
    for (int mi = 0; mi < 2; mi++)
        #pragma unroll
        for (int ni = 0; ni < 4; ni++)
            wmma::fill_fragment(acc[mi][ni], 0.f);

    // prologue
    load_tile(AhB[0], AlB[0], BhB[0], BlB[0], xh, xl, wh, wl, n, l0, 0, tid);
    asm volatile("cp.async.commit_group;" ::: "memory");

    for (int c = 0; c < 24; c++) {
        asm volatile("cp.async.wait_group 0;" ::: "memory");
        __syncthreads();
        if (c < 23) {
            int nb = (c + 1) & 1;
            load_tile(AhB[nb], AlB[nb], BhB[nb], BlB[nb], xh, xl, wh, wl, n, l0, c + 1, tid);
            asm volatile("cp.async.commit_group;" ::: "memory");
        }
        const __nv_bfloat16* Ahs = AhP[c & 1];
        const __nv_bfloat16* Als = AlP[c & 1];
        const __nv_bfloat16* Bhs = BhP[c & 1];
        const __nv_bfloat16* Bls = BlP[c & 1];
        #pragma unroll
        for (int kk = 0; kk < 2; kk++) {          // two k16 steps
            wmma::fragment<wmma::matrix_a, 16, 16, 16, __nv_bfloat16, wmma::row_major> ah[2], al[2];
            wmma::fragment<wmma::matrix_b, 16, 16, 16, __nv_bfloat16, wmma::row_major> bh[4], bl[4];
            #pragma unroll
            for (int mi = 0; mi < 2; mi++) {
                int ro = (warpM * 32 + mi * 16) * A_STRIDE + kk * 16;
                wmma::load_matrix_sync(ah[mi], Ahs + ro, A_STRIDE);
                wmma::load_matrix_sync(al[mi], Als + ro, A_STRIDE);
            }
            #pragma unroll
            for (int ni = 0; ni < 4; ni++) {
                int co = (kk * 16) * B_STRIDE + warpN * 64 + ni * 16;
                wmma::load_matrix_sync(bh[ni], Bhs + co, B_STRIDE);
                wmma::load_matrix_sync(bl[ni], Bls + co, B_STRIDE);
            }
            #pragma unroll
            for (int mi = 0; mi < 2; mi++)
                #pragma unroll
                for (int ni = 0; ni < 4; ni++) {
                    wmma::mma_sync(acc[mi][ni], ah[mi], bh[ni], acc[mi][ni]);
                    wmma::mma_sync(acc[mi][ni], ah[mi], bl[ni], acc[mi][ni]);
                    wmma::mma_sync(acc[mi][ni], al[mi], bh[ni], acc[mi][ni]);
                }
        }
    }

    // store accums to smem C
    #pragma unroll
    for (int mi = 0; mi < 2; mi++)
        #pragma unroll
        for (int ni = 0; ni < 4; ni++)
            wmma::store_matrix_sync(
                Cs + (warpM * 32 + mi * 16) * C_STRIDE + warpN * 64 + ni * 16,
                acc[mi][ni], C_STRIDE, wmma::mem_row_major);
    __syncthreads();

    // LN + relu epilogue: warp w handles rows w*8..w*8+7; lane owns cols lane*8..+8
    #pragma unroll
    for (int rr = 0; rr < 8; rr++) {
        const int row = wid * 8 + rr;
        const int grow = rows0 + row;
        const float* crow = Cs + row * C_STRIDE;
        float v[8];
        float4 v0 = *reinterpret_cast<const float4*>(crow + lane * 8);
        float4 v1 = *reinterpret_cast<const float4*>(crow + lane * 8 + 4);
        v[0]=v0.x; v[1]=v0.y; v[2]=v0.z; v[3]=v0.w;
        v[4]=v1.x; v[5]=v1.y; v[6]=v1.z; v[7]=v1.w;
        float sum = 0.f, sq = 0.f;
        #pragma unroll
        for (int k = 0; k < 8; k++) {
            v[k] += sBias[lane * 8 + k];
            sum += v[k]; sq += v[k] * v[k];
        }
        #pragma unroll
        for (int off = 16; off; off >>= 1) {
            sum += __shfl_xor_sync(0xffffffffu, sum, off);
            sq  += __shfl_xor_sync(0xffffffffu, sq,  off);
        }
        float mu = sum * (1.f / 256.f);
        float var = sq * (1.f / 256.f) - mu * mu;
        float rstd = rsqrtf(var + EPS);

        if (MODE == 0) {
            uint32_t uh[4], ul[4];
            #pragma unroll
            for (int k = 0; k < 4; k++) {
                float o0 = fmaxf((v[2*k]   - mu) * rstd * sG[lane*8 + 2*k]   + sB[lane*8 + 2*k],   0.f);
                float o1 = fmaxf((v[2*k+1] - mu) * rstd * sG[lane*8 + 2*k+1] + sB[lane*8 + 2*k+1], 0.f);
                __nv_bfloat16 h0 = __float2bfloat16(o0);
                __nv_bfloat16 h1 = __float2bfloat16(o1);
                __nv_bfloat16 s0 = __float2bfloat16(o0 - __bfloat162float(h0));
                __nv_bfloat16 s1 = __float2bfloat16(o1 - __bfloat162float(h1));
                __nv_bfloat162 th(h0, h1), tl(s0, s1);
                uh[k] = *reinterpret_cast<uint32_t*>(&th);
                ul[k] = *reinterpret_cast<uint32_t*>(&tl);
            }
            reinterpret_cast<uint4*>(houth + (size_t)grow * CC)[lane] =
                make_uint4(uh[0], uh[1], uh[2], uh[3]);
            reinterpret_cast<uint4*>(houtl + (size_t)grow * CC)[lane] =
                make_uint4(ul[0], ul[1], ul[2], ul[3]);
        } else {
            float p = 0.f;
            #pragma unroll
            for (int k = 0; k < 8; k++) {
                float o = fmaxf((v[k] - mu) * rstd * sG[lane*8 + k] + sB[lane*8 + k], 0.f);
                p += o * sLw[lane * 8 + k];
            }
            #pragma unroll
            for (int off = 16; off; off >>= 1)
                p += __shfl_xor_sync(0xffffffffu, p, off);
            if (lane == 0) dur[grow] = fmaxf(p + lb[0], 0.f);
        }
    }
}

// ---------------- inclusive cumsum of target per batch ----------------
__global__ void __launch_bounds__(512)
scan_kernel(const int* __restrict__ target, int* __restrict__ cum) {
    __shared__ int s[LL];
    const int n = blockIdx.x, t = threadIdx.x;
    s[t] = target[n * LL + t];
    __syncthreads();
    for (int off = 1; off < LL; off <<= 1) {
        int add = (t >= off) ? s[t - off] : 0;
        __syncthreads();
        s[t] += add;
        __syncthreads();
    }
    cum[n * LL + t] = s[t];
}

// ---------------- length regulation ----------------
__global__ void __launch_bounds__(256)
regulate_kernel(const float* __restrict__ x, const int* __restrict__ cum,
                float* __restrict__ out) {
    __shared__ int sc[LL];
    const int n  = blockIdx.y;
    const int t0 = blockIdx.x * 32;
    for (int i = threadIdx.x; i < LL; i += 256) sc[i] = cum[n * LL + i];
    __syncthreads();
    const int warp = threadIdx.x >> 5, lane = threadIdx.x & 31;
    const int total = sc[LL - 1];
    #pragma unroll
    for (int it = 0; it < 4; it++) {
        int t = t0 + warp * 4 + it;
        int j = -1;
        if (t < total) {
            int lo = 0, hi = LL - 1;
            while (lo < hi) { int mid = (lo + hi) >> 1; if (sc[mid] > t) hi = mid; else lo = mid + 1; }
            j = lo;
        }
        const float4* src = (j >= 0)
            ? reinterpret_cast<const float4*>(x + (size_t)(n * LL + j) * CC) : nullptr;
        float4* dst = reinterpret_cast<float4*>(out + ((size_t)n * MM + t) * CC);
        #pragma unroll
        for (int c = 0; c < 2; c++) {
            float4 v = (j >= 0) ? src[lane + c * 32] : make_float4(0.f, 0.f, 0.f, 0.f);
            dst[lane + c * 32] = v;
        }
    }
}

// ---------------- launch ----------------
extern "C" void kernel_launch(void* const* d_in, const int* in_sizes, int n_in,
                              void* d_out, int out_size) {
    const float* x       = (const float*)d_in[0];
    const float* conv1_w = (const float*)d_in[1];
    const float* conv1_b = (const float*)d_in[2];
    const float* ln1_g   = (const float*)d_in[3];
    const float* ln1_b   = (const float*)d_in[4];
    const float* conv2_w = (const float*)d_in[5];
    const float* conv2_b = (const float*)d_in[6];
    const float* ln2_g   = (const float*)d_in[7];
    const float* ln2_b   = (const float*)d_in[8];
    const float* lin_w   = (const float*)d_in[9];
    const float* lin_b   = (const float*)d_in[10];
    const int*   target  = (const int*)d_in[11];
    (void)n_in; (void)in_sizes;

    float* out_mel = (float*)d_out;                                  // [N, M, E]
    float* dur_out = (float*)d_out + ((size_t)out_size - NN * LL);   // [N, L]

    __nv_bfloat16 *xh, *xl, *h1h, *h1l, *w1h, *w1l, *w2h, *w2l; int* cum;
    cudaGetSymbolAddress((void**)&xh,  g_xh);
    cudaGetSymbolAddress((void**)&xl,  g_xl);
    cudaGetSymbolAddress((void**)&h1h, g_h1h);
    cudaGetSymbolAddress((void**)&h1l, g_h1l);
    cudaGetSymbolAddress((void**)&w1h, g_w1h);
    cudaGetSymbolAddress((void**)&w1l, g_w1l);
    cudaGetSymbolAddress((void**)&w2h, g_w2h);
    cudaGetSymbolAddress((void**)&w2l, g_w2l);
    cudaGetSymbolAddress((void**)&cum, g_cum);

    cudaFuncSetAttribute(conv_wmma_kernel<0>,
                         cudaFuncAttributeMaxDynamicSharedMemorySize, SM_TOTAL);
    cudaFuncSetAttribute(conv_wmma_kernel<1>,
                         cudaFuncAttributeMaxDynamicSharedMemorySize, SM_TOTAL);

    // prep
    prep_x_kernel<<<(ROWS * CC / 4) / 256, 256>>>(x, xh, xl);
    prep_w_kernel<<<(KTOT * CC) / 256, 256>>>(conv1_w, w1h, w1l);
    prep_w_kernel<<<(KTOT * CC) / 256, 256>>>(conv2_w, w2h, w2l);

    // duration predictor (conv+LN+relu fused, WMMA bf16x3)
    conv_wmma_kernel<0><<<ROWS / BM, 256, SM_TOTAL>>>(
        xh, xl, w1h, w1l, conv1_b, ln1_g, ln1_b, nullptr, nullptr, h1h, h1l, nullptr);
    conv_wmma_kernel<1><<<ROWS / BM, 256, SM_TOTAL>>>(
        h1h, h1l, w2h, w2l, conv2_b, ln2_g, ln2_b, lin_w, lin_b, nullptr, nullptr, dur_out);

    // length regulation
    scan_kernel<<<NN, LL>>>(target, cum);
    dim3 rgrid(MM / 32, NN);
    regulate_kernel<<<rgrid, 256>>>(x, cum, out_mel);
}